// round 1
// baseline (speedup 1.0000x reference)
#include <cuda_runtime.h>

#define EPS_F 1e-15f

static const int N_GCN  = 8192;
static const int DIN_   = 256;
static const int DOUT_  = 256;

// Scratch (no cudaMalloc allowed): degree scaling d[i], and g = diag(d) * (x @ W^T)
__device__ float g_d[8192];
__device__ float g_g[8192 * 256];

// ---------------------------------------------------------------------------
// Kernel A: per-row degree -> d[i] = rsqrt(1 + sum_j [A_ij > eps]),
// fused with the A passthrough copy (stream A once, write copy once).
// grid = N rows, 256 threads/row.
// ---------------------------------------------------------------------------
__global__ void deg_copy_kernel(const float* __restrict__ A,
                                float* __restrict__ Acopy,
                                int N, int doCopy) {
    int row = blockIdx.x;
    const float4* Ar = (const float4*)(A + (size_t)row * N);
    float4* Cr = (float4*)(Acopy + (size_t)row * N);
    int n4 = N >> 2;
    float s = 0.0f;
    for (int j = threadIdx.x; j < n4; j += blockDim.x) {
        float4 v = Ar[j];
        if (doCopy) Cr[j] = v;
        s += (v.x > EPS_F ? 1.0f : 0.0f);
        s += (v.y > EPS_F ? 1.0f : 0.0f);
        s += (v.z > EPS_F ? 1.0f : 0.0f);
        s += (v.w > EPS_F ? 1.0f : 0.0f);
    }
    __shared__ float red[256];
    red[threadIdx.x] = s;
    __syncthreads();
    for (int off = 128; off > 0; off >>= 1) {
        if (threadIdx.x < off) red[threadIdx.x] += red[threadIdx.x + off];
        __syncthreads();
    }
    if (threadIdx.x == 0) {
        g_d[row] = rsqrtf(1.0f + red[0]);
    }
}

// ---------------------------------------------------------------------------
// Kernel B: g[m][n] = d[m] * sum_k x[m][k] * W[n][k]
// 64x64 tile per CTA, 256 threads (16x16), 4x4 micro-tile, BK=16.
// ---------------------------------------------------------------------------
__global__ void xw_kernel(const float* __restrict__ x,
                          const float* __restrict__ W) {
    __shared__ float xs[16][68];  // xs[k][m_local]
    __shared__ float ws[16][68];  // ws[k][n_local] = W[n][k]

    int bm = blockIdx.x * 64;
    int bn = blockIdx.y * 64;
    int tid = threadIdx.x;
    int tx = tid & 15;
    int ty = tid >> 4;

    float acc[4][4];
#pragma unroll
    for (int i = 0; i < 4; i++)
#pragma unroll
        for (int j = 0; j < 4; j++) acc[i][j] = 0.0f;

    for (int kt = 0; kt < DIN_; kt += 16) {
        // Load x tile: 64 rows x 16 k = 256 float4, one per thread.
        {
            int r = tid >> 2;      // local row 0..63
            int c = tid & 3;       // float4 index within 16 k
            float4 v = *(const float4*)(x + (size_t)(bm + r) * DIN_ + kt + c * 4);
            xs[c * 4 + 0][r] = v.x;
            xs[c * 4 + 1][r] = v.y;
            xs[c * 4 + 2][r] = v.z;
            xs[c * 4 + 3][r] = v.w;
        }
        // Load W tile (transposed into ws[k][n]): 64 n-rows x 16 k.
        {
            int r = tid >> 2;      // local n 0..63
            int c = tid & 3;
            float4 v = *(const float4*)(W + (size_t)(bn + r) * DIN_ + kt + c * 4);
            ws[c * 4 + 0][r] = v.x;
            ws[c * 4 + 1][r] = v.y;
            ws[c * 4 + 2][r] = v.z;
            ws[c * 4 + 3][r] = v.w;
        }
        __syncthreads();
#pragma unroll
        for (int k = 0; k < 16; k++) {
            float4 a = *(const float4*)&xs[k][ty * 4];
            float4 b = *(const float4*)&ws[k][tx * 4];
            float av[4] = {a.x, a.y, a.z, a.w};
            float bv[4] = {b.x, b.y, b.z, b.w};
#pragma unroll
            for (int i = 0; i < 4; i++)
#pragma unroll
                for (int j = 0; j < 4; j++) acc[i][j] += av[i] * bv[j];
        }
        __syncthreads();
    }

#pragma unroll
    for (int i = 0; i < 4; i++) {
        int m = bm + ty * 4 + i;
        float dm = g_d[m];
#pragma unroll
        for (int j = 0; j < 4; j++) {
            int n = bn + tx * 4 + j;
            g_g[(size_t)m * DOUT_ + n] = dm * acc[i][j];
        }
    }
}

// ---------------------------------------------------------------------------
// Kernel C: out[m][n] = relu( d[m] * ( (A @ g)[m][n] + g[m][n] ) )
// (A_tilde = A + I folds into "+ g[m][n]".)
// 128x64 tile per CTA, 256 threads (16x16), 8x4 micro-tile, BK=16.
// ---------------------------------------------------------------------------
__global__ void agemm_kernel(const float* __restrict__ A,
                             float* __restrict__ out,
                             int N) {
    __shared__ float As[16][132];  // As[k][m_local]
    __shared__ float Bs[16][68];   // Bs[k][n_local]

    int bm = blockIdx.x * 128;
    int bn = blockIdx.y * 64;
    int tid = threadIdx.x;
    int tx = tid & 15;
    int ty = tid >> 4;

    float acc[8][4];
#pragma unroll
    for (int i = 0; i < 8; i++)
#pragma unroll
        for (int j = 0; j < 4; j++) acc[i][j] = 0.0f;

    for (int kt = 0; kt < N; kt += 16) {
        // Load A tile: 128 rows x 16 k = 512 float4, two per thread, transpose.
#pragma unroll
        for (int l = 0; l < 2; l++) {
            int t = tid + l * 256;
            int r = t >> 2;    // local m 0..127
            int c = t & 3;     // float4 within 16 k
            float4 v = *(const float4*)(A + (size_t)(bm + r) * N + kt + c * 4);
            As[c * 4 + 0][r] = v.x;
            As[c * 4 + 1][r] = v.y;
            As[c * 4 + 2][r] = v.z;
            As[c * 4 + 3][r] = v.w;
        }
        // Load g tile: 16 k-rows x 64 n = 256 float4, one per thread (no transpose).
        {
            int r = tid >> 4;  // local k 0..15
            int c = tid & 15;  // float4 within 64 n
            float4 v = *(const float4*)(g_g + (size_t)(kt + r) * DOUT_ + bn + c * 4);
            *(float4*)&Bs[r][c * 4] = v;
        }
        __syncthreads();
#pragma unroll
        for (int k = 0; k < 16; k++) {
            float4 a0 = *(const float4*)&As[k][ty * 8];
            float4 a1 = *(const float4*)&As[k][ty * 8 + 4];
            float4 b  = *(const float4*)&Bs[k][tx * 4];
            float av[8] = {a0.x, a0.y, a0.z, a0.w, a1.x, a1.y, a1.z, a1.w};
            float bv[4] = {b.x, b.y, b.z, b.w};
#pragma unroll
            for (int i = 0; i < 8; i++)
#pragma unroll
                for (int j = 0; j < 4; j++) acc[i][j] += av[i] * bv[j];
        }
        __syncthreads();
    }

#pragma unroll
    for (int i = 0; i < 8; i++) {
        int m = bm + ty * 8 + i;
        float dm = g_d[m];
#pragma unroll
        for (int j = 0; j < 4; j++) {
            int n = bn + tx * 4 + j;
            float v = dm * (acc[i][j] + g_g[(size_t)m * DOUT_ + n]);
            out[(size_t)m * DOUT_ + n] = fmaxf(v, 0.0f);
        }
    }
}

// ---------------------------------------------------------------------------
extern "C" void kernel_launch(void* const* d_in, const int* in_sizes, int n_in,
                              void* d_out, int out_size) {
    const float* x = (const float*)d_in[0];   // [8192, 256]
    const float* A = (const float*)d_in[1];   // [8192, 8192]
    const float* W = (const float*)d_in[2];   // [256, 256]
    float* out = (float*)d_out;

    const int N = N_GCN;
    const size_t out_elems = (size_t)N * DOUT_;

    // Second reference output is A itself; copy it if the harness expects it.
    int doCopy = ((size_t)out_size >= out_elems + (size_t)N * N) ? 1 : 0;
    float* Acopy = out + out_elems;  // only dereferenced when doCopy

    // 1. degrees + A passthrough copy
    deg_copy_kernel<<<N, 256>>>(A, doCopy ? Acopy : out /*unused*/, N, doCopy);

    // 2. g = diag(d) * (x @ W^T)
    dim3 gridB(N / 64, DOUT_ / 64);
    xw_kernel<<<gridB, 256>>>(x, W);

    // 3. out = relu(diag(d) * (A @ g + g))
    dim3 gridC(N / 128, DOUT_ / 64);
    agemm_kernel<<<gridC, 256>>>(A, out, N);
}

// round 3
// speedup vs baseline: 1.8794x; 1.8794x over previous
#include <cuda_runtime.h>
#include <cuda_fp16.h>
#include <cstdint>

#define EPS_F 1e-15f

static const int N_GCN  = 8192;
static const int DIN_   = 256;
static const int DOUT_  = 256;

// ---------------------------------------------------------------------------
// Scratch (__device__ globals; no cudaMalloc allowed)
// ---------------------------------------------------------------------------
__device__ float g_d[8192];
__device__ __align__(16) float  g_g[8192 * 256];            // g = d*(x@W^T) fp32, [m][n]
__device__ __align__(16) __half g_gT_h[256 * 8192];         // gT hi fp16, [n][k]
__device__ __align__(16) __half g_gT_l[256 * 8192];         // gT lo fp16, [n][k]

// ---------------------------------------------------------------------------
// PTX helpers (all plain sm_103-legal: ldmatrix / mma.sync / cp.async)
// ---------------------------------------------------------------------------
__device__ __forceinline__ uint32_t smem_to_u32(const void* p) {
    uint32_t a;
    asm("{ .reg .u64 t; cvta.to.shared.u64 t, %1; cvt.u32.u64 %0, t; }" : "=r"(a) : "l"(p));
    return a;
}

#define LDMX4(R, addr) \
    asm volatile("ldmatrix.sync.aligned.m8n8.x4.shared.b16 {%0,%1,%2,%3}, [%4];" \
        : "=r"((R)[0]), "=r"((R)[1]), "=r"((R)[2]), "=r"((R)[3]) : "r"(addr))

#define MMA16816(d, a, b0, b1) \
    asm volatile("mma.sync.aligned.m16n8k16.row.col.f32.f16.f16.f32 " \
        "{%0,%1,%2,%3}, {%4,%5,%6,%7}, {%8,%9}, {%0,%1,%2,%3};" \
        : "+f"((d)[0]), "+f"((d)[1]), "+f"((d)[2]), "+f"((d)[3]) \
        : "r"((a)[0]), "r"((a)[1]), "r"((a)[2]), "r"((a)[3]), "r"(b0), "r"(b1))

#define CP_ASYNC16(dst, src) \
    asm volatile("cp.async.cg.shared.global [%0], [%1], 16;" :: "r"(dst), "l"(src) : "memory")
#define CP_COMMIT() asm volatile("cp.async.commit_group;" ::: "memory")
#define CP_WAIT0()  asm volatile("cp.async.wait_group 0;" ::: "memory")

__device__ __forceinline__ uint32_t h2u(__half2 v) { return *reinterpret_cast<uint32_t*>(&v); }

// ---------------------------------------------------------------------------
// Kernel A: degrees + A passthrough copy (78% of HBM spec — keep)
// ---------------------------------------------------------------------------
__global__ void deg_copy_kernel(const float* __restrict__ A,
                                float* __restrict__ Acopy,
                                int N, int doCopy) {
    int row = blockIdx.x;
    const float4* Ar = (const float4*)(A + (size_t)row * N);
    float4* Cr = (float4*)(Acopy + (size_t)row * N);
    int n4 = N >> 2;
    float s = 0.0f;
    for (int j = threadIdx.x; j < n4; j += blockDim.x) {
        float4 v = Ar[j];
        if (doCopy) Cr[j] = v;
        s += (v.x > EPS_F ? 1.0f : 0.0f);
        s += (v.y > EPS_F ? 1.0f : 0.0f);
        s += (v.z > EPS_F ? 1.0f : 0.0f);
        s += (v.w > EPS_F ? 1.0f : 0.0f);
    }
    __shared__ float red[256];
    red[threadIdx.x] = s;
    __syncthreads();
    for (int off = 128; off > 0; off >>= 1) {
        if (threadIdx.x < off) red[threadIdx.x] += red[threadIdx.x + off];
        __syncthreads();
    }
    if (threadIdx.x == 0) g_d[row] = rsqrtf(1.0f + red[0]);
}

// ---------------------------------------------------------------------------
// Kernel B: g = d*(x@W^T) fp32 + transposed fp16 hi/lo splits for the MMA GEMM
// ---------------------------------------------------------------------------
__global__ void xw_kernel(const float* __restrict__ x,
                          const float* __restrict__ W) {
    __shared__ float xs[16][68];
    __shared__ float ws[16][68];

    int bm = blockIdx.x * 64;
    int bn = blockIdx.y * 64;
    int tid = threadIdx.x;
    int tx = tid & 15;
    int ty = tid >> 4;

    float acc[4][4];
#pragma unroll
    for (int i = 0; i < 4; i++)
#pragma unroll
        for (int j = 0; j < 4; j++) acc[i][j] = 0.0f;

    for (int kt = 0; kt < DIN_; kt += 16) {
        {
            int r = tid >> 2, c = tid & 3;
            float4 v = *(const float4*)(x + (size_t)(bm + r) * DIN_ + kt + c * 4);
            xs[c * 4 + 0][r] = v.x; xs[c * 4 + 1][r] = v.y;
            xs[c * 4 + 2][r] = v.z; xs[c * 4 + 3][r] = v.w;
        }
        {
            int r = tid >> 2, c = tid & 3;
            float4 v = *(const float4*)(W + (size_t)(bn + r) * DIN_ + kt + c * 4);
            ws[c * 4 + 0][r] = v.x; ws[c * 4 + 1][r] = v.y;
            ws[c * 4 + 2][r] = v.z; ws[c * 4 + 3][r] = v.w;
        }
        __syncthreads();
#pragma unroll
        for (int k = 0; k < 16; k++) {
            float4 a = *(const float4*)&xs[k][ty * 4];
            float4 b = *(const float4*)&ws[k][tx * 4];
            float av[4] = {a.x, a.y, a.z, a.w};
            float bv[4] = {b.x, b.y, b.z, b.w};
#pragma unroll
            for (int i = 0; i < 4; i++)
#pragma unroll
                for (int j = 0; j < 4; j++) acc[i][j] += av[i] * bv[j];
        }
        __syncthreads();
    }

    int m0 = bm + ty * 4;
    float dm[4];
#pragma unroll
    for (int i = 0; i < 4; i++) dm[i] = g_d[m0 + i];

#pragma unroll
    for (int j = 0; j < 4; j++) {
        int n = bn + tx * 4 + j;
        float gv[4];
#pragma unroll
        for (int i = 0; i < 4; i++) {
            gv[i] = dm[i] * acc[i][j];
            g_g[(size_t)(m0 + i) * DOUT_ + n] = gv[i];
        }
        __half2 h01 = __floats2half2_rn(gv[0], gv[1]);
        __half2 h23 = __floats2half2_rn(gv[2], gv[3]);
        float2 f01 = __half22float2(h01);
        float2 f23 = __half22float2(h23);
        __half2 l01 = __floats2half2_rn(gv[0] - f01.x, gv[1] - f01.y);
        __half2 l23 = __floats2half2_rn(gv[2] - f23.x, gv[3] - f23.y);
        *(uint2*)(&g_gT_h[(size_t)n * N_GCN + m0]) = make_uint2(h2u(h01), h2u(h23));
        *(uint2*)(&g_gT_l[(size_t)n * N_GCN + m0]) = make_uint2(h2u(l01), h2u(l23));
    }
}

// ---------------------------------------------------------------------------
// Kernel C: warp-MMA GEMM. out = relu(d * (A@g + g)).
// CTA 128x128, BK=16, 8 warps (2M x 4N), warp tile 64x32.
// fp16 3-term split: Ah*gh + Ah*gl + Al*gh  (residual ~2^-22).
// Static SMEM 48KB, double buffered; row stride 48B (conflict-free ldmatrix).
// ---------------------------------------------------------------------------
static const int BM = 128, BN = 128, BK = 16;
static const int TSTRIDE = 48;                // bytes per 16-fp16 row (padded)
static const int TILE_B  = 128 * TSTRIDE;     // 6144 B per tile
static const int BUF_B   = 4 * TILE_B;        // Ah, Al, Bh, Bl = 24576 B

__global__ void __launch_bounds__(256, 1)
agemm_mma(const float* __restrict__ A, float* __restrict__ out, int K) {
    __shared__ char smem[2 * BUF_B];          // 49152 B exactly
    uint32_t sbase = smem_to_u32(smem);

    int tid  = threadIdx.x;
    int lane = tid & 31;
    int wid  = tid >> 5;
    int wm = wid & 1;          // 0..1 -> 64-row block
    int wn = wid >> 1;         // 0..3 -> 32-col block
    int bm = blockIdx.x * BM;
    int bn = blockIdx.y * BN;

    // A loader mapping: each thread owns half a row of the 128x16 A tile
    int arow  = tid >> 1;                 // 0..127
    int ahalf = tid & 1;                  // 8 fp32 elems each
    const float* Aptr = A + (size_t)(bm + arow) * K + ahalf * 8;
    uint32_t a_soff = (uint32_t)arow * TSTRIDE + ahalf * 16;

    // ldmatrix per-lane offsets
    uint32_t aoff0 = (uint32_t)(wm * 64 + (lane & 15)) * TSTRIDE + ((lane >> 4) * 8) * 2;
    uint32_t brow  = (lane & 7) + ((lane >> 4) & 1) * 8;
    uint32_t boff0 = (uint32_t)(wn * 32 + brow) * TSTRIDE + (((lane >> 3) & 1) * 8) * 2;

    float acc[4][4][4];
#pragma unroll
    for (int f = 0; f < 4; f++)
#pragma unroll
        for (int n = 0; n < 4; n++)
#pragma unroll
            for (int e = 0; e < 4; e++) acc[f][n][e] = 0.0f;

    const int NC = K / BK;    // 512

    // ---- helpers ----
    auto issue_B = [&](int buf, int kt) {
#pragma unroll
        for (int j = 0; j < 2; j++) {
            int id = j * 256 + tid;               // 0..511
            int split = id >> 8;                  // 0=hi, 1=lo
            int rem = id & 255;
            int n = rem >> 1, seg = rem & 1;
            const __half* src = (split ? g_gT_l : g_gT_h) + (size_t)(bn + n) * K + seg * 8;
            uint32_t dst = sbase + buf * BUF_B + (2 + split) * TILE_B + n * TSTRIDE + seg * 16;
            CP_ASYNC16(dst, src + 0);
            (void)src;
        }
    };
    // NOTE: issue_B above computes src without kt; do it properly below.

    auto issue_B_kt = [&](int buf, int kt) {
#pragma unroll
        for (int j = 0; j < 2; j++) {
            int id = j * 256 + tid;
            int split = id >> 8;
            int rem = id & 255;
            int n = rem >> 1, seg = rem & 1;
            const __half* src = (split ? g_gT_l : g_gT_h) + (size_t)(bn + n) * K + kt + seg * 8;
            uint32_t dst = sbase + buf * BUF_B + (2 + split) * TILE_B + n * TSTRIDE + seg * 16;
            CP_ASYNC16(dst, src);
        }
    };

    auto store_A = [&](int buf, const float4& v0, const float4& v1) {
        __half2 h0 = __floats2half2_rn(v0.x, v0.y);
        __half2 h1 = __floats2half2_rn(v0.z, v0.w);
        __half2 h2 = __floats2half2_rn(v1.x, v1.y);
        __half2 h3 = __floats2half2_rn(v1.z, v1.w);
        float2 f0 = __half22float2(h0), f1 = __half22float2(h1);
        float2 f2 = __half22float2(h2), f3 = __half22float2(h3);
        __half2 l0 = __floats2half2_rn(v0.x - f0.x, v0.y - f0.y);
        __half2 l1 = __floats2half2_rn(v0.z - f1.x, v0.w - f1.y);
        __half2 l2 = __floats2half2_rn(v1.x - f2.x, v1.y - f2.y);
        __half2 l3 = __floats2half2_rn(v1.z - f3.x, v1.w - f3.y);
        char* base = smem + buf * BUF_B;
        *(uint4*)(base + a_soff)          = make_uint4(h2u(h0), h2u(h1), h2u(h2), h2u(h3));
        *(uint4*)(base + TILE_B + a_soff) = make_uint4(h2u(l0), h2u(l1), h2u(l2), h2u(l3));
    };

    // ---- prologue: chunk 0 -> buf 0 ----
    {
        float4 v0 = *(const float4*)(Aptr + 0);
        float4 v1 = *(const float4*)(Aptr + 4);
        issue_B_kt(0, 0);
        CP_COMMIT();
        store_A(0, v0, v1);
    }

    for (int i = 0; i < NC; i++) {
        int cur = i & 1, nxt = cur ^ 1;
        CP_WAIT0();
        __syncthreads();

        float4 v0, v1;
        bool more = (i + 1) < NC;
        if (more) {
            const float* Ap = Aptr + (size_t)(i + 1) * BK;
            v0 = *(const float4*)(Ap + 0);
            v1 = *(const float4*)(Ap + 4);
            issue_B_kt(nxt, (i + 1) * BK);
            CP_COMMIT();
        }

        // MMA on buf cur
        uint32_t sa_h = sbase + cur * BUF_B;
        uint32_t sa_l = sa_h + TILE_B;
        uint32_t sb_h = sa_h + 2 * TILE_B;
        uint32_t sb_l = sa_h + 3 * TILE_B;

        uint32_t ah[4][4], al[4][4], bh[2][4], bl[2][4];
#pragma unroll
        for (int f = 0; f < 4; f++) {
            LDMX4(ah[f], sa_h + aoff0 + f * (16 * TSTRIDE));
            LDMX4(al[f], sa_l + aoff0 + f * (16 * TSTRIDE));
        }
#pragma unroll
        for (int p = 0; p < 2; p++) {
            LDMX4(bh[p], sb_h + boff0 + p * (16 * TSTRIDE));
            LDMX4(bl[p], sb_l + boff0 + p * (16 * TSTRIDE));
        }
#pragma unroll
        for (int f = 0; f < 4; f++) {
#pragma unroll
            for (int nf = 0; nf < 4; nf++) {
                int p = nf >> 1, o = (nf & 1) * 2;
                MMA16816(acc[f][nf], ah[f], bh[p][o], bh[p][o + 1]);
                MMA16816(acc[f][nf], ah[f], bl[p][o], bl[p][o + 1]);
                MMA16816(acc[f][nf], al[f], bh[p][o], bh[p][o + 1]);
            }
        }

        if (more) store_A(nxt, v0, v1);
    }

    // ---- epilogue: out = relu(d * (acc + g)) ----
    int r0 = bm + wm * 64 + (lane >> 2);
    int c0 = bn + wn * 32 + (lane & 3) * 2;
#pragma unroll
    for (int f = 0; f < 4; f++) {
        int m1 = r0 + f * 16;
        int m2 = m1 + 8;
        float d1 = g_d[m1];
        float d2 = g_d[m2];
#pragma unroll
        for (int nf = 0; nf < 4; nf++) {
            int c = c0 + nf * 8;
            float2 g1 = *(const float2*)&g_g[(size_t)m1 * DOUT_ + c];
            float2 g2 = *(const float2*)&g_g[(size_t)m2 * DOUT_ + c];
            float2 o1, o2;
            o1.x = fmaxf(d1 * (acc[f][nf][0] + g1.x), 0.0f);
            o1.y = fmaxf(d1 * (acc[f][nf][1] + g1.y), 0.0f);
            o2.x = fmaxf(d2 * (acc[f][nf][2] + g2.x), 0.0f);
            o2.y = fmaxf(d2 * (acc[f][nf][3] + g2.y), 0.0f);
            *(float2*)&out[(size_t)m1 * DOUT_ + c] = o1;
            *(float2*)&out[(size_t)m2 * DOUT_ + c] = o2;
        }
    }
}

// ---------------------------------------------------------------------------
extern "C" void kernel_launch(void* const* d_in, const int* in_sizes, int n_in,
                              void* d_out, int out_size) {
    const float* x = (const float*)d_in[0];   // [8192, 256]
    const float* A = (const float*)d_in[1];   // [8192, 8192]
    const float* W = (const float*)d_in[2];   // [256, 256]
    float* out = (float*)d_out;

    const int N = N_GCN;
    const size_t out_elems = (size_t)N * DOUT_;

    int doCopy = ((size_t)out_size >= out_elems + (size_t)N * N) ? 1 : 0;
    float* Acopy = out + out_elems;

    // 1. degrees + A passthrough copy
    deg_copy_kernel<<<N, 256>>>(A, doCopy ? Acopy : out, N, doCopy);

    // 2. g = diag(d)*(x@W^T) fp32 + fp16 hi/lo transposed splits
    dim3 gridB(N / 64, DOUT_ / 64);
    xw_kernel<<<gridB, 256>>>(x, W);

    // 3. out = relu(diag(d)*(A@g + g)) via mma.sync fp16-split tensor cores
    dim3 gridC(N / BM, DOUT_ / BN);
    agemm_mma<<<gridC, 256>>>(A, out, N);
}

// round 4
// speedup vs baseline: 2.1605x; 1.1496x over previous
#include <cuda_runtime.h>
#include <cuda_fp16.h>
#include <cstdint>

#define EPS_F 1e-15f

static const int N_GCN  = 8192;
static const int DIN_   = 256;
static const int DOUT_  = 256;

// ---------------------------------------------------------------------------
// Scratch (__device__ globals; no cudaMalloc allowed)
// ---------------------------------------------------------------------------
__device__ float g_d[8192];
__device__ __align__(16) float  g_g[8192 * 256];            // g = d*(x@W^T) fp32, [m][n]
__device__ __align__(16) __half g_gT_h[256 * 8192];         // gT hi fp16, [n][k]
__device__ __align__(16) __half g_gT_l[256 * 8192];         // gT lo fp16, [n][k]

// ---------------------------------------------------------------------------
// PTX helpers (plain sm_103-legal: ldmatrix / mma.sync / cp.async)
// ---------------------------------------------------------------------------
__device__ __forceinline__ uint32_t smem_to_u32(const void* p) {
    uint32_t a;
    asm("{ .reg .u64 t; cvta.to.shared.u64 t, %1; cvt.u32.u64 %0, t; }" : "=r"(a) : "l"(p));
    return a;
}

#define LDMX4(R, addr) \
    asm volatile("ldmatrix.sync.aligned.m8n8.x4.shared.b16 {%0,%1,%2,%3}, [%4];" \
        : "=r"((R)[0]), "=r"((R)[1]), "=r"((R)[2]), "=r"((R)[3]) : "r"(addr))

#define MMA16816(d, a, b0, b1) \
    asm volatile("mma.sync.aligned.m16n8k16.row.col.f32.f16.f16.f32 " \
        "{%0,%1,%2,%3}, {%4,%5,%6,%7}, {%8,%9}, {%0,%1,%2,%3};" \
        : "+f"((d)[0]), "+f"((d)[1]), "+f"((d)[2]), "+f"((d)[3]) \
        : "r"((a)[0]), "r"((a)[1]), "r"((a)[2]), "r"((a)[3]), "r"(b0), "r"(b1))

#define CP_ASYNC16(dst, src) \
    asm volatile("cp.async.cg.shared.global [%0], [%1], 16;" :: "r"(dst), "l"(src) : "memory")
#define CP_COMMIT() asm volatile("cp.async.commit_group;" ::: "memory")
#define CP_WAIT0()  asm volatile("cp.async.wait_group 0;" ::: "memory")

__device__ __forceinline__ uint32_t h2u(__half2 v) { return *reinterpret_cast<uint32_t*>(&v); }

// ---------------------------------------------------------------------------
// Kernel A: degrees + A passthrough copy (78% of HBM spec — keep)
// ---------------------------------------------------------------------------
__global__ void deg_copy_kernel(const float* __restrict__ A,
                                float* __restrict__ Acopy,
                                int N, int doCopy) {
    int row = blockIdx.x;
    const float4* Ar = (const float4*)(A + (size_t)row * N);
    float4* Cr = (float4*)(Acopy + (size_t)row * N);
    int n4 = N >> 2;
    float s = 0.0f;
    for (int j = threadIdx.x; j < n4; j += blockDim.x) {
        float4 v = Ar[j];
        if (doCopy) Cr[j] = v;
        s += (v.x > EPS_F ? 1.0f : 0.0f);
        s += (v.y > EPS_F ? 1.0f : 0.0f);
        s += (v.z > EPS_F ? 1.0f : 0.0f);
        s += (v.w > EPS_F ? 1.0f : 0.0f);
    }
    __shared__ float red[256];
    red[threadIdx.x] = s;
    __syncthreads();
    for (int off = 128; off > 0; off >>= 1) {
        if (threadIdx.x < off) red[threadIdx.x] += red[threadIdx.x + off];
        __syncthreads();
    }
    if (threadIdx.x == 0) g_d[row] = rsqrtf(1.0f + red[0]);
}

// ---------------------------------------------------------------------------
// Kernel B: g = d*(x@W^T) fp32 + transposed fp16 hi/lo splits for the MMA GEMM
// ---------------------------------------------------------------------------
__global__ void xw_kernel(const float* __restrict__ x,
                          const float* __restrict__ W) {
    __shared__ float xs[16][68];
    __shared__ float ws[16][68];

    int bm = blockIdx.x * 64;
    int bn = blockIdx.y * 64;
    int tid = threadIdx.x;
    int tx = tid & 15;
    int ty = tid >> 4;

    float acc[4][4];
#pragma unroll
    for (int i = 0; i < 4; i++)
#pragma unroll
        for (int j = 0; j < 4; j++) acc[i][j] = 0.0f;

    for (int kt = 0; kt < DIN_; kt += 16) {
        {
            int r = tid >> 2, c = tid & 3;
            float4 v = *(const float4*)(x + (size_t)(bm + r) * DIN_ + kt + c * 4);
            xs[c * 4 + 0][r] = v.x; xs[c * 4 + 1][r] = v.y;
            xs[c * 4 + 2][r] = v.z; xs[c * 4 + 3][r] = v.w;
        }
        {
            int r = tid >> 2, c = tid & 3;
            float4 v = *(const float4*)(W + (size_t)(bn + r) * DIN_ + kt + c * 4);
            ws[c * 4 + 0][r] = v.x; ws[c * 4 + 1][r] = v.y;
            ws[c * 4 + 2][r] = v.z; ws[c * 4 + 3][r] = v.w;
        }
        __syncthreads();
#pragma unroll
        for (int k = 0; k < 16; k++) {
            float4 a = *(const float4*)&xs[k][ty * 4];
            float4 b = *(const float4*)&ws[k][tx * 4];
            float av[4] = {a.x, a.y, a.z, a.w};
            float bv[4] = {b.x, b.y, b.z, b.w};
#pragma unroll
            for (int i = 0; i < 4; i++)
#pragma unroll
                for (int j = 0; j < 4; j++) acc[i][j] += av[i] * bv[j];
        }
        __syncthreads();
    }

    int m0 = bm + ty * 4;
    float dm[4];
#pragma unroll
    for (int i = 0; i < 4; i++) dm[i] = g_d[m0 + i];

#pragma unroll
    for (int j = 0; j < 4; j++) {
        int n = bn + tx * 4 + j;
        float gv[4];
#pragma unroll
        for (int i = 0; i < 4; i++) {
            gv[i] = dm[i] * acc[i][j];
            g_g[(size_t)(m0 + i) * DOUT_ + n] = gv[i];
        }
        __half2 h01 = __floats2half2_rn(gv[0], gv[1]);
        __half2 h23 = __floats2half2_rn(gv[2], gv[3]);
        float2 f01 = __half22float2(h01);
        float2 f23 = __half22float2(h23);
        __half2 l01 = __floats2half2_rn(gv[0] - f01.x, gv[1] - f01.y);
        __half2 l23 = __floats2half2_rn(gv[2] - f23.x, gv[3] - f23.y);
        *(uint2*)(&g_gT_h[(size_t)n * N_GCN + m0]) = make_uint2(h2u(h01), h2u(h23));
        *(uint2*)(&g_gT_l[(size_t)n * N_GCN + m0]) = make_uint2(h2u(l01), h2u(l23));
    }
}

// ---------------------------------------------------------------------------
// Kernel C: warp-MMA GEMM. out = relu(d * (A@g + g)).
// CTA 128x128, BK=32, 8 warps (2M x 4N), warp tile 64x32.
// fp16 3-term split: Ah*gh + Ah*gl + Al*gh  (residual ~2^-22).
// Dynamic SMEM 80KB double buffered; row stride 80B => LDSM conflict-free.
// Term-major MMA order: same-acc reuse distance 16 MMAs (covers HMMA latency).
// ---------------------------------------------------------------------------
static const int BM = 128, BN = 128, BK = 32;
static const int TSTRIDE = 80;                 // bytes per 32-fp16 row (64B + 16 pad)
static const int TILE_B  = 128 * TSTRIDE;      // 10240 B
static const int BUF_B   = 4 * TILE_B;         // Ah, Al, Bh, Bl = 40960 B
static const int SMEM_TOTAL_C = 2 * BUF_B;     // 81920 B (dynamic)

__global__ void __launch_bounds__(256, 1)
agemm_mma(const float* __restrict__ A, float* __restrict__ out, int K) {
    extern __shared__ char smem[];
    uint32_t sbase = smem_to_u32(smem);

    int tid  = threadIdx.x;
    int lane = tid & 31;
    int wid  = tid >> 5;
    int wm = wid & 1;          // 0..1 -> 64-row block
    int wn = wid >> 1;         // 0..3 -> 32-col block
    int bm = blockIdx.x * BM;
    int bn = blockIdx.y * BN;

    // A loader: each thread owns half a row (16 of 32 k) of the 128x32 A tile
    int arow  = tid >> 1;
    int ahalf = tid & 1;
    const float* Aptr = A + (size_t)(bm + arow) * K + ahalf * 16;
    uint32_t a_soff = (uint32_t)arow * TSTRIDE + ahalf * 32;

    // ldmatrix per-lane base offsets (k-half and f/p block offsets added later)
    uint32_t aoff0 = (uint32_t)(wm * 64 + (lane & 15)) * TSTRIDE + (lane >> 4) * 16;
    uint32_t brow  = (lane & 7) + ((lane >> 4) & 1) * 8;
    uint32_t boff0 = (uint32_t)(wn * 32 + brow) * TSTRIDE + ((lane >> 3) & 1) * 16;

    float acc[4][4][4];
#pragma unroll
    for (int f = 0; f < 4; f++)
#pragma unroll
        for (int n = 0; n < 4; n++)
#pragma unroll
            for (int e = 0; e < 4; e++) acc[f][n][e] = 0.0f;

    const int NC = K / BK;    // 256

    auto issue_B = [&](int buf, int kt) {
#pragma unroll
        for (int j = 0; j < 4; j++) {
            int id = j * 256 + tid;            // 0..1023
            int split = id >> 9;               // 0=hi, 1=lo
            int rem = id & 511;
            int n = rem >> 2, seg = rem & 3;   // 4 x 16B segments = 32 fp16
            const __half* src = (split ? g_gT_l : g_gT_h) + (size_t)(bn + n) * K + kt + seg * 8;
            uint32_t dst = sbase + buf * BUF_B + (2 + split) * TILE_B + n * TSTRIDE + seg * 16;
            CP_ASYNC16(dst, src);
        }
    };

    auto store_A = [&](int buf, const float4* v) {
        uint32_t hi[8], lo[8];
#pragma unroll
        for (int q = 0; q < 4; q++) {
            __half2 ha = __floats2half2_rn(v[q].x, v[q].y);
            __half2 hb = __floats2half2_rn(v[q].z, v[q].w);
            float2 fa = __half22float2(ha), fb = __half22float2(hb);
            __half2 la = __floats2half2_rn(v[q].x - fa.x, v[q].y - fa.y);
            __half2 lb = __floats2half2_rn(v[q].z - fb.x, v[q].w - fb.y);
            hi[q * 2] = h2u(ha); hi[q * 2 + 1] = h2u(hb);
            lo[q * 2] = h2u(la); lo[q * 2 + 1] = h2u(lb);
        }
        char* base = smem + buf * BUF_B;
        *(uint4*)(base + a_soff)               = make_uint4(hi[0], hi[1], hi[2], hi[3]);
        *(uint4*)(base + a_soff + 16)          = make_uint4(hi[4], hi[5], hi[6], hi[7]);
        *(uint4*)(base + TILE_B + a_soff)      = make_uint4(lo[0], lo[1], lo[2], lo[3]);
        *(uint4*)(base + TILE_B + a_soff + 16) = make_uint4(lo[4], lo[5], lo[6], lo[7]);
    };

    // ---- prologue: chunk 0 -> buf 0 ----
    {
        float4 v[4];
#pragma unroll
        for (int q = 0; q < 4; q++) v[q] = *(const float4*)(Aptr + q * 4);
        issue_B(0, 0);
        CP_COMMIT();
        store_A(0, v);
    }

    for (int i = 0; i < NC; i++) {
        int cur = i & 1, nxt = cur ^ 1;
        CP_WAIT0();
        __syncthreads();

        float4 v[4];
        bool more = (i + 1) < NC;
        if (more) {
            const float* Ap = Aptr + (size_t)(i + 1) * BK;
#pragma unroll
            for (int q = 0; q < 4; q++) v[q] = *(const float4*)(Ap + q * 4);
            issue_B(nxt, (i + 1) * BK);
            CP_COMMIT();
        }

        uint32_t sa_h = sbase + cur * BUF_B;
        uint32_t sa_l = sa_h + TILE_B;
        uint32_t sb_h = sa_h + 2 * TILE_B;
        uint32_t sb_l = sa_h + 3 * TILE_B;

#pragma unroll
        for (int kh = 0; kh < 2; kh++) {
            uint32_t ah[4][4], al[4][4], bh[2][4], bl[2][4];
            uint32_t ka = aoff0 + kh * 32;
            uint32_t kb = boff0 + kh * 32;
#pragma unroll
            for (int f = 0; f < 4; f++) LDMX4(ah[f], sa_h + ka + f * (16 * TSTRIDE));
#pragma unroll
            for (int p = 0; p < 2; p++) LDMX4(bh[p], sb_h + kb + p * (16 * TSTRIDE));
#pragma unroll
            for (int f = 0; f < 4; f++) LDMX4(al[f], sa_l + ka + f * (16 * TSTRIDE));
#pragma unroll
            for (int p = 0; p < 2; p++) LDMX4(bl[p], sb_l + kb + p * (16 * TSTRIDE));

            // term-major: same-acc reuse distance = 16 MMAs
#pragma unroll
            for (int f = 0; f < 4; f++)
#pragma unroll
                for (int nf = 0; nf < 4; nf++) {
                    int p = nf >> 1, o = (nf & 1) * 2;
                    MMA16816(acc[f][nf], ah[f], bh[p][o], bh[p][o + 1]);
                }
#pragma unroll
            for (int f = 0; f < 4; f++)
#pragma unroll
                for (int nf = 0; nf < 4; nf++) {
                    int p = nf >> 1, o = (nf & 1) * 2;
                    MMA16816(acc[f][nf], ah[f], bl[p][o], bl[p][o + 1]);
                }
#pragma unroll
            for (int f = 0; f < 4; f++)
#pragma unroll
                for (int nf = 0; nf < 4; nf++) {
                    int p = nf >> 1, o = (nf & 1) * 2;
                    MMA16816(acc[f][nf], al[f], bh[p][o], bh[p][o + 1]);
                }
        }

        if (more) store_A(nxt, v);
    }

    // ---- epilogue: out = relu(d * (acc + g)) ----
    int r0 = bm + wm * 64 + (lane >> 2);
    int c0 = bn + wn * 32 + (lane & 3) * 2;
#pragma unroll
    for (int f = 0; f < 4; f++) {
        int m1 = r0 + f * 16;
        int m2 = m1 + 8;
        float d1 = g_d[m1];
        float d2 = g_d[m2];
#pragma unroll
        for (int nf = 0; nf < 4; nf++) {
            int c = c0 + nf * 8;
            float2 g1 = *(const float2*)&g_g[(size_t)m1 * DOUT_ + c];
            float2 g2 = *(const float2*)&g_g[(size_t)m2 * DOUT_ + c];
            float2 o1, o2;
            o1.x = fmaxf(d1 * (acc[f][nf][0] + g1.x), 0.0f);
            o1.y = fmaxf(d1 * (acc[f][nf][1] + g1.y), 0.0f);
            o2.x = fmaxf(d2 * (acc[f][nf][2] + g2.x), 0.0f);
            o2.y = fmaxf(d2 * (acc[f][nf][3] + g2.y), 0.0f);
            *(float2*)&out[(size_t)m1 * DOUT_ + c] = o1;
            *(float2*)&out[(size_t)m2 * DOUT_ + c] = o2;
        }
    }
}

// ---------------------------------------------------------------------------
extern "C" void kernel_launch(void* const* d_in, const int* in_sizes, int n_in,
                              void* d_out, int out_size) {
    const float* x = (const float*)d_in[0];   // [8192, 256]
    const float* A = (const float*)d_in[1];   // [8192, 8192]
    const float* W = (const float*)d_in[2];   // [256, 256]
    float* out = (float*)d_out;

    const int N = N_GCN;
    const size_t out_elems = (size_t)N * DOUT_;

    int doCopy = ((size_t)out_size >= out_elems + (size_t)N * N) ? 1 : 0;
    float* Acopy = out + out_elems;

    cudaFuncSetAttribute(agemm_mma, cudaFuncAttributeMaxDynamicSharedMemorySize,
                         SMEM_TOTAL_C);

    // 1. degrees + A passthrough copy
    deg_copy_kernel<<<N, 256>>>(A, doCopy ? Acopy : out, N, doCopy);

    // 2. g = diag(d)*(x@W^T) fp32 + fp16 hi/lo transposed splits
    dim3 gridB(N / 64, DOUT_ / 64);
    xw_kernel<<<gridB, 256>>>(x, W);

    // 3. out = relu(diag(d)*(A@g + g)) via mma.sync fp16-split tensor cores
    dim3 gridC(N / BM, DOUT_ / BN);
    agemm_mma<<<gridC, 256, SMEM_TOTAL_C>>>(A, out, N);
}

// round 5
// speedup vs baseline: 2.4995x; 1.1569x over previous
#include <cuda_runtime.h>
#include <cuda_fp16.h>
#include <cstdint>

#define EPS_F 1e-15f

static const int N_GCN  = 8192;
static const int DIN_   = 256;
static const int DOUT_  = 256;

// ---------------------------------------------------------------------------
// Scratch (__device__ globals; no cudaMalloc allowed)
// ---------------------------------------------------------------------------
__device__ float g_d[8192];
__device__ __align__(16) float  g_g[8192 * 256];            // g = d*(x@W^T) fp32, [m][n]
__device__ __align__(16) __half g_gT_h[256 * 8192];         // gT hi fp16, [n][k]
__device__ __align__(16) __half g_gT_l[256 * 8192];         // gT lo fp16, [n][k]

// ---------------------------------------------------------------------------
// PTX helpers (plain sm_103-legal: ldmatrix / mma.sync / cp.async)
// ---------------------------------------------------------------------------
__device__ __forceinline__ uint32_t smem_to_u32(const void* p) {
    uint32_t a;
    asm("{ .reg .u64 t; cvta.to.shared.u64 t, %1; cvt.u32.u64 %0, t; }" : "=r"(a) : "l"(p));
    return a;
}

#define LDMX4(R, addr) \
    asm volatile("ldmatrix.sync.aligned.m8n8.x4.shared.b16 {%0,%1,%2,%3}, [%4];" \
        : "=r"((R)[0]), "=r"((R)[1]), "=r"((R)[2]), "=r"((R)[3]) : "r"(addr))

#define MMA16816(d, a, b0, b1) \
    asm volatile("mma.sync.aligned.m16n8k16.row.col.f32.f16.f16.f32 " \
        "{%0,%1,%2,%3}, {%4,%5,%6,%7}, {%8,%9}, {%0,%1,%2,%3};" \
        : "+f"((d)[0]), "+f"((d)[1]), "+f"((d)[2]), "+f"((d)[3]) \
        : "r"((a)[0]), "r"((a)[1]), "r"((a)[2]), "r"((a)[3]), "r"(b0), "r"(b1))

#define CP_ASYNC16(dst, src) \
    asm volatile("cp.async.cg.shared.global [%0], [%1], 16;" :: "r"(dst), "l"(src) : "memory")
#define CP_COMMIT() asm volatile("cp.async.commit_group;" ::: "memory")
#define CP_WAIT0()  asm volatile("cp.async.wait_group 0;" ::: "memory")

__device__ __forceinline__ uint32_t h2u(__half2 v) { return *reinterpret_cast<uint32_t*>(&v); }

// ---------------------------------------------------------------------------
// Kernel A: read-only degree computation (copy moved into the GEMM)
// ---------------------------------------------------------------------------
__global__ void deg_kernel(const float* __restrict__ A, int N) {
    int row = blockIdx.x;
    const float4* Ar = (const float4*)(A + (size_t)row * N);
    int n4 = N >> 2;
    float s = 0.0f;
    for (int j = threadIdx.x; j < n4; j += blockDim.x) {
        float4 v = Ar[j];
        s += (v.x > EPS_F ? 1.0f : 0.0f);
        s += (v.y > EPS_F ? 1.0f : 0.0f);
        s += (v.z > EPS_F ? 1.0f : 0.0f);
        s += (v.w > EPS_F ? 1.0f : 0.0f);
    }
    __shared__ float red[256];
    red[threadIdx.x] = s;
    __syncthreads();
    for (int off = 128; off > 0; off >>= 1) {
        if (threadIdx.x < off) red[threadIdx.x] += red[threadIdx.x + off];
        __syncthreads();
    }
    if (threadIdx.x == 0) g_d[row] = rsqrtf(1.0f + red[0]);
}

// ---------------------------------------------------------------------------
// Kernel B: g = d*(x@W^T) fp32 + transposed fp16 hi/lo splits for the MMA GEMM
// ---------------------------------------------------------------------------
__global__ void xw_kernel(const float* __restrict__ x,
                          const float* __restrict__ W) {
    __shared__ float xs[16][68];
    __shared__ float ws[16][68];

    int bm = blockIdx.x * 64;
    int bn = blockIdx.y * 64;
    int tid = threadIdx.x;
    int tx = tid & 15;
    int ty = tid >> 4;

    float acc[4][4];
#pragma unroll
    for (int i = 0; i < 4; i++)
#pragma unroll
        for (int j = 0; j < 4; j++) acc[i][j] = 0.0f;

    for (int kt = 0; kt < DIN_; kt += 16) {
        {
            int r = tid >> 2, c = tid & 3;
            float4 v = *(const float4*)(x + (size_t)(bm + r) * DIN_ + kt + c * 4);
            xs[c * 4 + 0][r] = v.x; xs[c * 4 + 1][r] = v.y;
            xs[c * 4 + 2][r] = v.z; xs[c * 4 + 3][r] = v.w;
        }
        {
            int r = tid >> 2, c = tid & 3;
            float4 v = *(const float4*)(W + (size_t)(bn + r) * DIN_ + kt + c * 4);
            ws[c * 4 + 0][r] = v.x; ws[c * 4 + 1][r] = v.y;
            ws[c * 4 + 2][r] = v.z; ws[c * 4 + 3][r] = v.w;
        }
        __syncthreads();
#pragma unroll
        for (int k = 0; k < 16; k++) {
            float4 a = *(const float4*)&xs[k][ty * 4];
            float4 b = *(const float4*)&ws[k][tx * 4];
            float av[4] = {a.x, a.y, a.z, a.w};
            float bv[4] = {b.x, b.y, b.z, b.w};
#pragma unroll
            for (int i = 0; i < 4; i++)
#pragma unroll
                for (int j = 0; j < 4; j++) acc[i][j] += av[i] * bv[j];
        }
        __syncthreads();
    }

    int m0 = bm + ty * 4;
    float dm[4];
#pragma unroll
    for (int i = 0; i < 4; i++) dm[i] = g_d[m0 + i];

#pragma unroll
    for (int j = 0; j < 4; j++) {
        int n = bn + tx * 4 + j;
        float gv[4];
#pragma unroll
        for (int i = 0; i < 4; i++) {
            gv[i] = dm[i] * acc[i][j];
            g_g[(size_t)(m0 + i) * DOUT_ + n] = gv[i];
        }
        __half2 h01 = __floats2half2_rn(gv[0], gv[1]);
        __half2 h23 = __floats2half2_rn(gv[2], gv[3]);
        float2 f01 = __half22float2(h01);
        float2 f23 = __half22float2(h23);
        __half2 l01 = __floats2half2_rn(gv[0] - f01.x, gv[1] - f01.y);
        __half2 l23 = __floats2half2_rn(gv[2] - f23.x, gv[3] - f23.y);
        *(uint2*)(&g_gT_h[(size_t)n * N_GCN + m0]) = make_uint2(h2u(h01), h2u(h23));
        *(uint2*)(&g_gT_l[(size_t)n * N_GCN + m0]) = make_uint2(h2u(l01), h2u(l23));
    }
}

// ---------------------------------------------------------------------------
// Kernel C: warp-MMA GEMM. out = relu(d * (A@g + g)) + fused A passthrough copy.
// CTA 128x128, BK=32, 8 warps (2M x 4N), warp tile 64x32.
// fp16 2-term split: Ah*gh + Ah*gl   (A residual dropped, ~1.7e-4 rel)
// Dynamic SMEM 60KB double buffered (Ah, Bh, Bl); stride 80B, conflict-free.
// A copy: CTA (bx,by) copies chunks with (i>>7)==by -> perfectly balanced.
// ---------------------------------------------------------------------------
static const int BM = 128, BN = 128, BK = 32;
static const int TSTRIDE = 80;
static const int TILE_B  = 128 * TSTRIDE;      // 10240 B
static const int BUF_B   = 3 * TILE_B;         // Ah, Bh, Bl = 30720 B
static const int SMEM_TOTAL_C = 2 * BUF_B;     // 61440 B (dynamic)

__global__ void __launch_bounds__(256, 1)
agemm_mma(const float* __restrict__ A, float* __restrict__ out,
          float* __restrict__ Acopy, int doCopy, int K) {
    extern __shared__ char smem[];
    uint32_t sbase = smem_to_u32(smem);

    int tid  = threadIdx.x;
    int lane = tid & 31;
    int wid  = tid >> 5;
    int wm = wid & 1;
    int wn = wid >> 1;
    int bm = blockIdx.x * BM;
    int bn = blockIdx.y * BN;
    int by = blockIdx.y;

    // A loader: each thread owns half a row (16 of 32 k) of the 128x32 A tile
    int arow  = tid >> 1;
    int ahalf = tid & 1;
    const float* Aptr = A + (size_t)(bm + arow) * K + ahalf * 16;
    float* Cptr = Acopy ? (Acopy + (size_t)(bm + arow) * K + ahalf * 16) : (float*)0;
    uint32_t a_soff = (uint32_t)arow * TSTRIDE + ahalf * 32;

    uint32_t aoff0 = (uint32_t)(wm * 64 + (lane & 15)) * TSTRIDE + (lane >> 4) * 16;
    uint32_t brow  = (lane & 7) + ((lane >> 4) & 1) * 8;
    uint32_t boff0 = (uint32_t)(wn * 32 + brow) * TSTRIDE + ((lane >> 3) & 1) * 16;

    float acc[4][4][4];
#pragma unroll
    for (int f = 0; f < 4; f++)
#pragma unroll
        for (int n = 0; n < 4; n++)
#pragma unroll
            for (int e = 0; e < 4; e++) acc[f][n][e] = 0.0f;

    const int NC = K / BK;    // 256

    auto issue_B = [&](int buf, int kt) {
#pragma unroll
        for (int j = 0; j < 4; j++) {
            int id = j * 256 + tid;            // 0..1023
            int split = id >> 9;               // 0=hi, 1=lo
            int rem = id & 511;
            int n = rem >> 2, seg = rem & 3;
            const __half* src = (split ? g_gT_l : g_gT_h) + (size_t)(bn + n) * K + kt + seg * 8;
            uint32_t dst = sbase + buf * BUF_B + (1 + split) * TILE_B + n * TSTRIDE + seg * 16;
            CP_ASYNC16(dst, src);
        }
    };

    // store A hi tile to smem; optionally copy the raw fp32 chunk to Acopy
    auto store_A = [&](int buf, const float4* v, int chunk) {
        uint32_t hi[8];
#pragma unroll
        for (int q = 0; q < 4; q++) {
            __half2 ha = __floats2half2_rn(v[q].x, v[q].y);
            __half2 hb = __floats2half2_rn(v[q].z, v[q].w);
            hi[q * 2] = h2u(ha); hi[q * 2 + 1] = h2u(hb);
        }
        char* base = smem + buf * BUF_B;
        *(uint4*)(base + a_soff)      = make_uint4(hi[0], hi[1], hi[2], hi[3]);
        *(uint4*)(base + a_soff + 16) = make_uint4(hi[4], hi[5], hi[6], hi[7]);
        if (doCopy && (chunk >> 7) == by) {
            float* cp = Cptr + (size_t)chunk * BK;
#pragma unroll
            for (int q = 0; q < 4; q++) *(float4*)(cp + q * 4) = v[q];
        }
    };

    // ---- prologue: chunk 0 -> buf 0 ----
    {
        float4 v[4];
#pragma unroll
        for (int q = 0; q < 4; q++) v[q] = *(const float4*)(Aptr + q * 4);
        issue_B(0, 0);
        CP_COMMIT();
        store_A(0, v, 0);
    }

    for (int i = 0; i < NC; i++) {
        int cur = i & 1, nxt = cur ^ 1;
        CP_WAIT0();
        __syncthreads();

        float4 v[4];
        bool more = (i + 1) < NC;
        if (more) {
            const float* Ap = Aptr + (size_t)(i + 1) * BK;
#pragma unroll
            for (int q = 0; q < 4; q++) v[q] = *(const float4*)(Ap + q * 4);
            issue_B(nxt, (i + 1) * BK);
            CP_COMMIT();
        }

        uint32_t sa_h = sbase + cur * BUF_B;
        uint32_t sb_h = sa_h + TILE_B;
        uint32_t sb_l = sa_h + 2 * TILE_B;

#pragma unroll
        for (int kh = 0; kh < 2; kh++) {
            uint32_t ah[4][4], bh[2][4], bl[2][4];
            uint32_t ka = aoff0 + kh * 32;
            uint32_t kb = boff0 + kh * 32;
#pragma unroll
            for (int f = 0; f < 4; f++) LDMX4(ah[f], sa_h + ka + f * (16 * TSTRIDE));
#pragma unroll
            for (int p = 0; p < 2; p++) LDMX4(bh[p], sb_h + kb + p * (16 * TSTRIDE));
#pragma unroll
            for (int p = 0; p < 2; p++) LDMX4(bl[p], sb_l + kb + p * (16 * TSTRIDE));

            // term-major: same-acc reuse distance = 16 MMAs
#pragma unroll
            for (int f = 0; f < 4; f++)
#pragma unroll
                for (int nf = 0; nf < 4; nf++) {
                    int p = nf >> 1, o = (nf & 1) * 2;
                    MMA16816(acc[f][nf], ah[f], bh[p][o], bh[p][o + 1]);
                }
#pragma unroll
            for (int f = 0; f < 4; f++)
#pragma unroll
                for (int nf = 0; nf < 4; nf++) {
                    int p = nf >> 1, o = (nf & 1) * 2;
                    MMA16816(acc[f][nf], ah[f], bl[p][o], bl[p][o + 1]);
                }
        }

        if (more) store_A(nxt, v, i + 1);
    }

    // ---- epilogue: out = relu(d * (acc + g)) ----
    int r0 = bm + wm * 64 + (lane >> 2);
    int c0 = bn + wn * 32 + (lane & 3) * 2;
#pragma unroll
    for (int f = 0; f < 4; f++) {
        int m1 = r0 + f * 16;
        int m2 = m1 + 8;
        float d1 = g_d[m1];
        float d2 = g_d[m2];
#pragma unroll
        for (int nf = 0; nf < 4; nf++) {
            int c = c0 + nf * 8;
            float2 g1 = *(const float2*)&g_g[(size_t)m1 * DOUT_ + c];
            float2 g2 = *(const float2*)&g_g[(size_t)m2 * DOUT_ + c];
            float2 o1, o2;
            o1.x = fmaxf(d1 * (acc[f][nf][0] + g1.x), 0.0f);
            o1.y = fmaxf(d1 * (acc[f][nf][1] + g1.y), 0.0f);
            o2.x = fmaxf(d2 * (acc[f][nf][2] + g2.x), 0.0f);
            o2.y = fmaxf(d2 * (acc[f][nf][3] + g2.y), 0.0f);
            *(float2*)&out[(size_t)m1 * DOUT_ + c] = o1;
            *(float2*)&out[(size_t)m2 * DOUT_ + c] = o2;
        }
    }
}

// ---------------------------------------------------------------------------
extern "C" void kernel_launch(void* const* d_in, const int* in_sizes, int n_in,
                              void* d_out, int out_size) {
    const float* x = (const float*)d_in[0];   // [8192, 256]
    const float* A = (const float*)d_in[1];   // [8192, 8192]
    const float* W = (const float*)d_in[2];   // [256, 256]
    float* out = (float*)d_out;

    const int N = N_GCN;
    const size_t out_elems = (size_t)N * DOUT_;

    int doCopy = ((size_t)out_size >= out_elems + (size_t)N * N) ? 1 : 0;
    float* Acopy = doCopy ? (out + out_elems) : (float*)0;

    cudaFuncSetAttribute(agemm_mma, cudaFuncAttributeMaxDynamicSharedMemorySize,
                         SMEM_TOTAL_C);

    // 1. degrees (read-only)
    deg_kernel<<<N, 256>>>(A, N);

    // 2. g = diag(d)*(x@W^T) fp32 + fp16 hi/lo transposed splits
    dim3 gridB(N / 64, DOUT_ / 64);
    xw_kernel<<<gridB, 256>>>(x, W);

    // 3. out = relu(diag(d)*(A@g + g)) via mma.sync + fused A copy
    dim3 gridC(N / BM, DOUT_ / BN);
    agemm_mma<<<gridC, 256, SMEM_TOTAL_C>>>(A, out, Acopy, doCopy, N);
}